// round 5
// baseline (speedup 1.0000x reference)
#include <cuda_runtime.h>
#include <cuda_bf16.h>

// Problem constants
#define BATCH   2
#define SEQ     2048
#define DMODEL  1024
#define NHEAD   16
#define DK      64
#define MROWS   (BATCH * SEQ)       // 4096

// ---------------------------------------------------------------------------
// Scratch (no allocations allowed -> device globals)
// ---------------------------------------------------------------------------
__device__ float g_Q[MROWS * DMODEL];
__device__ float g_K[MROWS * DMODEL];
__device__ float g_V[MROWS * DMODEL];
__device__ float g_X[MROWS * DMODEL];   // attention output (pre out-proj)

// ---------------------------------------------------------------------------
// Packed fp32x2 helpers (Blackwell double-rate fp32 path)
// ---------------------------------------------------------------------------
__device__ __forceinline__ unsigned long long pack2(float lo, float hi) {
    unsigned long long r;
    asm("mov.b64 %0, {%1, %2};" : "=l"(r) : "f"(lo), "f"(hi));
    return r;
}
__device__ __forceinline__ float2 unpack2(unsigned long long x) {
    float2 r;
    asm("mov.b64 {%0, %1}, %2;" : "=f"(r.x), "=f"(r.y) : "l"(x));
    return r;
}
__device__ __forceinline__ unsigned long long ffma2(unsigned long long a,
                                                    unsigned long long b,
                                                    unsigned long long c) {
    unsigned long long d;
    asm("fma.rn.f32x2 %0, %1, %2, %3;" : "=l"(d) : "l"(a), "l"(b), "l"(c));
    return d;
}
__device__ __forceinline__ unsigned long long fmul2(unsigned long long a,
                                                    unsigned long long b) {
    unsigned long long d;
    asm("mul.rn.f32x2 %0, %1, %2;" : "=l"(d) : "l"(a), "l"(b));
    return d;
}

// cp.async helpers (16B, bypass-L1 .cg path)
__device__ __forceinline__ void cp_async16(void* smem_ptr, const void* gptr) {
    unsigned saddr = (unsigned)__cvta_generic_to_shared(smem_ptr);
    asm volatile("cp.async.cg.shared.global [%0], [%1], 16;"
                 :: "r"(saddr), "l"(gptr) : "memory");
}
__device__ __forceinline__ void cp_commit() {
    asm volatile("cp.async.commit_group;" ::: "memory");
}
__device__ __forceinline__ void cp_wait0() {
    asm volatile("cp.async.wait_group 0;" ::: "memory");
}

// ---------------------------------------------------------------------------
// NT GEMM: C[m,n] = sum_k A[m,k] * W[n,k];  tiles 128x128x16, 256 threads.
// Double-buffered smem, ONE __syncthreads per k-tile, register prefetch.
// Thread (ty,tx): rows m0+8ty..+7, cols n0+8tx..+7 (4 f32x2 pairs).
// A duplicated in smem so the f32x2 'a' operand loads need no packing.
// ---------------------------------------------------------------------------
__device__ __forceinline__ void gemm_nt_body(const float* __restrict__ A,
                                             const float* __restrict__ W,
                                             float* __restrict__ C) {
    __shared__ __align__(16) float As2[2][16][256];   // [buf][k][2*m] duplicated
    __shared__ __align__(16) float Bs[2][16][128];    // [buf][k][n]

    const int tid = threadIdx.x;
    const int m0 = blockIdx.y * 128;
    const int n0 = blockIdx.x * 128;
    const int ty = tid >> 4;      // 0..15
    const int tx = tid & 15;      // 0..15

    const int r0 = tid >> 2;      // 0..63
    const int r1 = r0 + 64;
    const int c4 = tid & 3;       // float4 column within 16-wide k slab

    const float4* A4 = (const float4*)A;
    const float4* W4 = (const float4*)W;

    unsigned long long acc[8][4];
#pragma unroll
    for (int i = 0; i < 8; i++)
#pragma unroll
        for (int p = 0; p < 4; p++) acc[i][p] = 0ull;

    float4 pa0, pa1, pb0, pb1;

#define GEMM_LDG(kt)                                               \
    do {                                                           \
        const int ko = (kt) * 4;                                   \
        pa0 = A4[(size_t)(m0 + r0) * 256 + ko + c4];               \
        pa1 = A4[(size_t)(m0 + r1) * 256 + ko + c4];               \
        pb0 = W4[(size_t)(n0 + r0) * 256 + ko + c4];               \
        pb1 = W4[(size_t)(n0 + r1) * 256 + ko + c4];               \
    } while (0)

#define GEMM_STS(buf)                                              \
    do {                                                           \
        const int kc = c4 * 4;                                     \
        *(float2*)&As2[buf][kc + 0][2 * r0] = make_float2(pa0.x, pa0.x); \
        *(float2*)&As2[buf][kc + 1][2 * r0] = make_float2(pa0.y, pa0.y); \
        *(float2*)&As2[buf][kc + 2][2 * r0] = make_float2(pa0.z, pa0.z); \
        *(float2*)&As2[buf][kc + 3][2 * r0] = make_float2(pa0.w, pa0.w); \
        *(float2*)&As2[buf][kc + 0][2 * r1] = make_float2(pa1.x, pa1.x); \
        *(float2*)&As2[buf][kc + 1][2 * r1] = make_float2(pa1.y, pa1.y); \
        *(float2*)&As2[buf][kc + 2][2 * r1] = make_float2(pa1.z, pa1.z); \
        *(float2*)&As2[buf][kc + 3][2 * r1] = make_float2(pa1.w, pa1.w); \
        Bs[buf][kc + 0][r0] = pb0.x;                               \
        Bs[buf][kc + 1][r0] = pb0.y;                               \
        Bs[buf][kc + 2][r0] = pb0.z;                               \
        Bs[buf][kc + 3][r0] = pb0.w;                               \
        Bs[buf][kc + 0][r1] = pb1.x;                               \
        Bs[buf][kc + 1][r1] = pb1.y;                               \
        Bs[buf][kc + 2][r1] = pb1.z;                               \
        Bs[buf][kc + 3][r1] = pb1.w;                               \
    } while (0)

    // prologue: tile 0 staged, tile 1 prefetched
    GEMM_LDG(0);
    GEMM_STS(0);
    GEMM_LDG(1);

    for (int kt = 0; kt < 64; kt++) {
        const int cur = kt & 1;
        __syncthreads();   // publishes buf[cur]; guarantees buf[cur^1] is free

        if (kt < 63) GEMM_STS(cur ^ 1);   // stage tile kt+1
        if (kt < 62) GEMM_LDG(kt + 2);    // prefetch tile kt+2

        // ---- compute 16 k-steps from buf[cur] ----
#pragma unroll
        for (int kk = 0; kk < 16; kk++) {
            unsigned long long a2[8];
            const ulonglong2* Ar = (const ulonglong2*)&As2[cur][kk][ty * 16];
#pragma unroll
            for (int i = 0; i < 4; i++) {
                ulonglong2 t = Ar[i];
                a2[2 * i]     = t.x;
                a2[2 * i + 1] = t.y;
            }
            const ulonglong2* Br = (const ulonglong2*)&Bs[cur][kk][8 * tx];
            ulonglong2 tb0 = Br[0];
            ulonglong2 tb1 = Br[1];
            unsigned long long b2[4] = {tb0.x, tb0.y, tb1.x, tb1.y};
#pragma unroll
            for (int i = 0; i < 8; i++)
#pragma unroll
                for (int p = 0; p < 4; p++)
                    acc[i][p] = ffma2(a2[i], b2[p], acc[i][p]);
        }
    }
#undef GEMM_LDG
#undef GEMM_STS

    // ---- epilogue: 8 contiguous floats per row -> two 16B stores ----
    float* Cr = C + (size_t)(m0 + ty * 8) * 1024 + n0 + 8 * tx;
#pragma unroll
    for (int i = 0; i < 8; i++) {
        *(ulonglong2*)(Cr + (size_t)i * 1024)     = make_ulonglong2(acc[i][0], acc[i][1]);
        *(ulonglong2*)(Cr + (size_t)i * 1024 + 4) = make_ulonglong2(acc[i][2], acc[i][3]);
    }
}

__global__ void __launch_bounds__(256, 2)
mha_gemm_qkv(const float* __restrict__ q, const float* __restrict__ k,
             const float* __restrict__ v, const float* __restrict__ wq,
             const float* __restrict__ wk, const float* __restrict__ wv) {
    const int z = blockIdx.z;
    const float* A = (z == 0) ? q : (z == 1) ? k : v;
    const float* W = (z == 0) ? wq : (z == 1) ? wk : wv;
    float* C = (z == 0) ? g_Q : (z == 1) ? g_K : g_V;
    gemm_nt_body(A, W, C);
}

__global__ void __launch_bounds__(256, 2)
mha_gemm_out(const float* __restrict__ wo, float* __restrict__ out) {
    gemm_nt_body(g_X, wo, out);
}

// ---------------------------------------------------------------------------
// Flash attention: CTA = 128 query rows x one (batch, head); 128 threads,
// thread t owns row q0+t. K/V tiles (32x64) double-buffered via cp.async,
// one __syncthreads per tile. Scores staged in smem (stride 33, no conflicts).
// ---------------------------------------------------------------------------
#define ATT_BM 128
#define ATT_BN 32
#define ATT_SS_STRIDE 33
#define ATT_TILE_F (ATT_BN * DK)                    // 2048 floats per K or V buffer
#define ATT_SMEM_FLOATS (4 * ATT_TILE_F + ATT_BM * ATT_SS_STRIDE)
#define ATT_SMEM_BYTES (ATT_SMEM_FLOATS * 4)        // 49664 bytes

__device__ __forceinline__ void att_issue_tile(float* KsB, float* VsB,
                                               int b, int h, int j0, int t) {
    const float* Kg = g_K + ((size_t)(b * SEQ + j0)) * DMODEL + h * DK;
    const float* Vg = g_V + ((size_t)(b * SEQ + j0)) * DMODEL + h * DK;
#pragma unroll
    for (int it = 0; it < 4; it++) {
        const int idx = t + it * 128;       // 0..511 over 32 rows x 16 float4
        const int r = idx >> 4;
        const int c = idx & 15;
        cp_async16(KsB + r * DK + c * 4, Kg + (size_t)r * DMODEL + c * 4);
        cp_async16(VsB + r * DK + c * 4, Vg + (size_t)r * DMODEL + c * 4);
    }
    cp_commit();
}

__global__ void __launch_bounds__(128, 3)
mha_flash_attn(const int* __restrict__ mask) {
    extern __shared__ __align__(16) float smf[];
    float* Ks[2] = {smf, smf + ATT_TILE_F};
    float* Vs[2] = {smf + 2 * ATT_TILE_F, smf + 3 * ATT_TILE_F};
    float* Ss    = smf + 4 * ATT_TILE_F;

    const int t  = threadIdx.x;
    const int q0 = blockIdx.x * ATT_BM;
    const int bh = blockIdx.y;
    const int b  = bh >> 4;
    const int h  = bh & 15;
    const int row = b * SEQ + q0 + t;

    // q row (64 floats) as 32 packed pairs
    unsigned long long q2[32];
    {
        const ulonglong2* Qr =
            (const ulonglong2*)(g_Q + (size_t)row * DMODEL + h * DK);
#pragma unroll
        for (int i = 0; i < 16; i++) {
            ulonglong2 tq = Qr[i];
            q2[2 * i]     = tq.x;
            q2[2 * i + 1] = tq.y;
        }
    }
    unsigned long long o2[32];
#pragma unroll
    for (int i = 0; i < 32; i++) o2[i] = 0ull;

    float m_i = -1e30f;
    float l_i = 0.0f;

    const int* mrow = mask + ((size_t)b * SEQ + (q0 + t)) * SEQ;
    float* ssrow = Ss + t * ATT_SS_STRIDE;

    // prologue: tile 0 in flight
    att_issue_tile(Ks[0], Vs[0], b, h, 0, t);

    const int NT = SEQ / ATT_BN;   // 64 tiles
    for (int n = 0; n < NT; n++) {
        const int cur = n & 1;
        const int j0 = n * ATT_BN;

        cp_wait0();
        __syncthreads();           // tile n visible; prev compute done

        if (n + 1 < NT)
            att_issue_tile(Ks[cur ^ 1], Vs[cur ^ 1], b, h, j0 + ATT_BN, t);

        const float* Kc = Ks[cur];
        const float* Vc = Vs[cur];

        // ---- scores: s_j = (q . K_j) / 8, masked; 4 independent fma chains ----
        float tmax = -1e30f;
#pragma unroll
        for (int j4 = 0; j4 < ATT_BN / 4; j4++) {
            const int4 mv = *(const int4*)(mrow + j0 + j4 * 4);
            const int mvals[4] = {mv.x, mv.y, mv.z, mv.w};
#pragma unroll
            for (int jj = 0; jj < 4; jj++) {
                const int j = j4 * 4 + jj;
                const ulonglong2* k2 = (const ulonglong2*)(Kc + j * DK);
                unsigned long long ax0 = 0ull, ax1 = 0ull, ay0 = 0ull, ay1 = 0ull;
#pragma unroll
                for (int c = 0; c < 16; c += 2) {
                    ulonglong2 kv0 = k2[c];
                    ulonglong2 kv1 = k2[c + 1];
                    ax0 = ffma2(q2[2 * c],     kv0.x, ax0);
                    ay0 = ffma2(q2[2 * c + 1], kv0.y, ay0);
                    ax1 = ffma2(q2[2 * c + 2], kv1.x, ax1);
                    ay1 = ffma2(q2[2 * c + 3], kv1.y, ay1);
                }
                float2 x0 = unpack2(ax0);
                float2 x1 = unpack2(ax1);
                float2 y0 = unpack2(ay0);
                float2 y1 = unpack2(ay1);
                float s = ((x0.x + x0.y) + (x1.x + x1.y)) +
                          ((y0.x + y0.y) + (y1.x + y1.y));
                s *= 0.125f;
                if (mvals[jj] == 0) s = -1e9f;
                ssrow[j] = s;
                tmax = fmaxf(tmax, s);
            }
        }

        // ---- online softmax rescale ----
        const float m_new = fmaxf(m_i, tmax);
        const float alpha = __expf(m_i - m_new);
        l_i *= alpha;
        {
            const unsigned long long a2 = pack2(alpha, alpha);
#pragma unroll
            for (int c = 0; c < 32; c++) o2[c] = fmul2(o2[c], a2);
        }

        // ---- accumulate P @ V ----
        for (int j = 0; j < ATT_BN; j++) {
            const float p = __expf(ssrow[j] - m_new);
            l_i += p;
            const unsigned long long p2 = pack2(p, p);
            const ulonglong2* v2 = (const ulonglong2*)(Vc + j * DK);
#pragma unroll
            for (int c = 0; c < 16; c++) {
                ulonglong2 vv = v2[c];
                o2[2 * c]     = ffma2(p2, vv.x, o2[2 * c]);
                o2[2 * c + 1] = ffma2(p2, vv.y, o2[2 * c + 1]);
            }
        }
        m_i = m_new;
    }

    // ---- epilogue: O = acc / l ----
    const float inv = 1.0f / l_i;
    const unsigned long long inv2 = pack2(inv, inv);
    ulonglong2* Or = (ulonglong2*)(g_X + (size_t)row * DMODEL + h * DK);
#pragma unroll
    for (int c = 0; c < 16; c++)
        Or[c] = make_ulonglong2(fmul2(o2[2 * c], inv2), fmul2(o2[2 * c + 1], inv2));
}

// ---------------------------------------------------------------------------
// Launch
// Inputs (metadata order): q, k, v, w_q, w_k, w_v, w_o, mask
// ---------------------------------------------------------------------------
extern "C" void kernel_launch(void* const* d_in, const int* in_sizes, int n_in,
                              void* d_out, int out_size) {
    const float* q  = (const float*)d_in[0];
    const float* k  = (const float*)d_in[1];
    const float* v  = (const float*)d_in[2];
    const float* wq = (const float*)d_in[3];
    const float* wk = (const float*)d_in[4];
    const float* wv = (const float*)d_in[5];
    const float* wo = (const float*)d_in[6];
    const int* mask = (const int*)d_in[7];
    float* out = (float*)d_out;

    cudaFuncSetAttribute(mha_flash_attn,
                         cudaFuncAttributeMaxDynamicSharedMemorySize,
                         ATT_SMEM_BYTES);

    // Q/K/V projections: grid (N/128, M/128, 3)
    dim3 gqkv(DMODEL / 128, MROWS / 128, 3);
    mha_gemm_qkv<<<gqkv, 256>>>(q, k, v, wq, wk, wv);

    // attention: grid (S/128, B*H)
    dim3 gatt(SEQ / ATT_BM, BATCH * NHEAD);
    mha_flash_attn<<<gatt, 128, ATT_SMEM_BYTES>>>(mask);

    // output projection
    dim3 gout(DMODEL / 128, MROWS / 128, 1);
    mha_gemm_out<<<gout, 256>>>(wo, out);
}